// round 10
// baseline (speedup 1.0000x reference)
#include <cuda_runtime.h>

#define N_   8
#define D_   64
#define H_   64
#define W_   64
#define HW_  4096
#define CHW  (D_*HW_)   /* 262144 */
#define KK   25
#define PW   72          /* padded smem row width: 4 | 64 | 4 */
#define NT   320         /* fused kernel threads: (g:16, r:5, ds:4) */

// Scratch (static __device__ allocation — allowed)
__device__ int   g_cnt[2][N_];
__device__ float g_inv[N_];

__global__ void zero_cnt_kernel() {
    int t = threadIdx.x;
    if (t < 2*N_) ((int*)g_cnt)[t] = 0;
}

__global__ void count_kernel(const float* __restrict__ cur, const float* __restrict__ prev) {
    int arr = blockIdx.y;
    int n   = blockIdx.z;
    const float4* p = (const float4*)((arr == 0 ? cur : prev) + (size_t)n * CHW);
    const int nv = CHW / 4;
    int cnt = 0;
    for (int i = blockIdx.x * blockDim.x + threadIdx.x; i < nv; i += gridDim.x * blockDim.x) {
        float4 v = p[i];
        cnt += (v.x != 0.f) + (v.y != 0.f) + (v.z != 0.f) + (v.w != 0.f);
    }
    #pragma unroll
    for (int o = 16; o; o >>= 1) cnt += __shfl_xor_sync(0xffffffffu, cnt, o);
    __shared__ int ws[8];
    int lane = threadIdx.x & 31, wid = threadIdx.x >> 5;
    if (lane == 0) ws[wid] = cnt;
    __syncthreads();
    if (wid == 0) {
        int c = (lane < (int)(blockDim.x >> 5)) ? ws[lane] : 0;
        #pragma unroll
        for (int o = 4; o; o >>= 1) c += __shfl_xor_sync(0xffffffffu, c, o);
        if (lane == 0) atomicAdd(&g_cnt[arr][n], c);
    }
}

__global__ void finalize_kernel() {
    int t = threadIdx.x;
    if (t < N_) {
        float a = (float)g_cnt[0][t] + 1e-8f;
        float b = (float)g_cnt[1][t] + 1e-8f;
        g_inv[t] = 1.0f / (a * b);
    }
}

// Fully fused: one CTA per (row y, batch n), 320 threads = (g:16, r:5, ds:4).
//   Phase A: 25-tap affinity partial dots (vector LDS.128, zero-padded halo).
//   Phase B: relu/mass/normalize -> ws[64][25].
//   Phase C: prev region refilled with prev_mem; weighted gather, smem r-reduce.
// NOTE: phase C needs NO zero pads — out-of-window taps carry weight 0.
__global__ __launch_bounds__(NT) void fused_kernel(const float* __restrict__ cur,
                                                   const float* __restrict__ prev,
                                                   const float* __restrict__ pm,
                                                   float* __restrict__ out) {
    extern __shared__ float sm[];
    float* cur_s  = sm;            // [64 d][64 x]
    float* prev_s = sm + 4096;     // [(r*64+d)][72]  (4-col pads each side)
    // overlays:
    float* partial = prev_s;       // [4 ds][5 r][16 g][20] = 6400 fl (A->B; prev data dead)
    float* ws_s    = sm;           // [64 x][25]           = 1600 fl (B->C; cur data dead)
    float* psum    = sm;           // [5 r][4 ds][16 g][8] = 2560 fl (C, after wreg cached)

    const int y = blockIdx.x, n = blockIdx.y;
    const int t = threadIdx.x;
    const int g  = t & 15;
    const int r  = (t >> 4) % 5;
    const int ds = t / 80;
    const float* curb  = cur  + (size_t)n * CHW;
    const float* prevb = prev + (size_t)n * CHW;
    const float* pmb   = pm   + (size_t)n * CHW;
    const float4 Z4 = make_float4(0.f, 0.f, 0.f, 0.f);

    // ---- zero ONLY the pad columns; fill cur region ----
    for (int i = t; i < 640; i += NT) {
        int row = i >> 1, side = i & 1;
        *(float4*)(prev_s + row * PW + side * 68) = Z4;
    }
    for (int i = t; i < 1024; i += NT) {
        int d = i >> 4, x4 = i & 15;
        *(float4*)(cur_s + d * 64 + 4 * x4) =
            *(const float4*)(curb + d * HW_ + y * W_ + 4 * x4);
    }
    // ---- fill prev interiors; invalid halo rows get zeros (fold into fill) ----
    for (int i = t; i < 5 * 1024; i += NT) {
        int rr = i >> 10, rem = i & 1023;
        int d = rem >> 4, x4 = rem & 15;
        int yy = y - 2 + rr;
        bool valid = (yy >= 0) && (yy < H_);
        *(float4*)(prev_s + (rr * 64 + d) * PW + 4 + 4 * x4) =
            valid ? *(const float4*)(prevb + d * HW_ + yy * W_ + 4 * x4) : Z4;
    }
    __syncthreads();

    // ---- Phase A: affinity partial dots. thread=(g,r,ds); 20 accs, 16 d ----
    {
        const float* prow = prev_s + (r * 64) * PW + 4 * g;
        const float* crow = cur_s + 4 * g;
        float acc[20];
        #pragma unroll
        for (int i = 0; i < 20; i++) acc[i] = 0.f;
        const int d0 = ds * 16;
        #pragma unroll 4
        for (int d = d0; d < d0 + 16; d++) {
            float4 c4 = *(const float4*)(crow + d * 64);
            float4 a  = *(const float4*)(prow + d * PW);
            float4 b  = *(const float4*)(prow + d * PW + 4);
            float4 e  = *(const float4*)(prow + d * PW + 8);
            float v[12] = {a.x,a.y,a.z,a.w, b.x,b.y,b.z,b.w, e.x,e.y,e.z,e.w};
            float c[4]  = {c4.x, c4.y, c4.z, c4.w};
            #pragma unroll
            for (int j = 0; j < 4; j++)
                #pragma unroll
                for (int dxi = 0; dxi < 5; dxi++)
                    acc[j*5+dxi] = fmaf(c[j], v[j + dxi + 2], acc[j*5+dxi]);
        }
        __syncthreads();   // prev data consumed; partial overlay goes live
        float* pp = partial + ((ds * 5 + r) * 16 + g) * 20;
        #pragma unroll
        for (int i = 0; i < 20; i++) pp[i] = acc[i];
    }
    __syncthreads();

    // ---- Phase B: relu, mass, normalize -> ws[64][25] ----
    if (t < 64) {
        const int x = t, gg = x >> 2, j = x & 3;
        float coef[KK];
        float m = 0.f;
        #pragma unroll
        for (int rr = 0; rr < 5; rr++)
            #pragma unroll
            for (int dxi = 0; dxi < 5; dxi++) {
                float s = 0.f;
                #pragma unroll
                for (int dd = 0; dd < 4; dd++)
                    s += partial[((dd * 5 + rr) * 16 + gg) * 20 + j*5 + dxi];
                s = fmaxf(s, 0.f);
                coef[rr*5 + dxi] = s;
                m += s;
            }
        const bool  zero = fabsf(m * g_inv[n]) < 1e-7f;
        const float invm = zero ? 0.f : 1.0f / m;
        #pragma unroll
        for (int k = 0; k < KK; k++)
            ws_s[x * KK + k] = zero ? (k == 12 ? 1.0f : 0.0f) : coef[k] * invm;
    }
    __syncthreads();

    // ---- Phase C fill: prev_mem interiors (pads irrelevant: weight=0 there) ----
    for (int i = t; i < 5 * 1024; i += NT) {
        int rr = i >> 10, rem = i & 1023;
        int d = rem >> 4, x4 = rem & 15;
        int yy = y - 2 + rr;
        if (yy >= 0 && yy < H_)
            *(float4*)(prev_s + (rr * 64 + d) * PW + 4 + 4 * x4) =
                *(const float4*)(pmb + d * HW_ + yy * W_ + 4 * x4);
    }

    // cache this thread's 20 weights (pixel-group g, row r) BEFORE psum overlay
    float wreg[20];
    #pragma unroll
    for (int j = 0; j < 4; j++)
        #pragma unroll
        for (int dxi = 0; dxi < 5; dxi++)
            wreg[j*5+dxi] = ws_s[(4*g + j) * KK + r*5 + dxi];
    __syncthreads();   // ws reads done everywhere; psum overlay (sm[0..)) goes live

    // ---- Phase C: weighted gather. 8 chunks of 2 d; smem reduce over r ----
    const float* prow = prev_s + (r * 64) * PW + 4 * g;
    const int xr = t & 63, dq = (t >> 6) & 3;   // reader role (t < 256)
    float* ob = out + (size_t)n * CHW + y * W_ + xr;

    for (int ch = 0; ch < 8; ch++) {
        const int dbase = ds * 16 + ch * 2;
        float po[8];
        #pragma unroll
        for (int i = 0; i < 8; i++) po[i] = 0.f;
        #pragma unroll
        for (int dd = 0; dd < 2; dd++) {
            int d = dbase + dd;
            float4 a = *(const float4*)(prow + d * PW);
            float4 b = *(const float4*)(prow + d * PW + 4);
            float4 e = *(const float4*)(prow + d * PW + 8);
            float v[12] = {a.x,a.y,a.z,a.w, b.x,b.y,b.z,b.w, e.x,e.y,e.z,e.w};
            #pragma unroll
            for (int j = 0; j < 4; j++)
                #pragma unroll
                for (int dxi = 0; dxi < 5; dxi++)
                    po[j*2+dd] = fmaf(wreg[j*5+dxi], v[j + dxi + 2], po[j*2+dd]);
        }
        {
            float* pp = psum + ((r * 4 + ds) * 16 + g) * 8;
            #pragma unroll
            for (int i = 0; i < 8; i++) pp[i] = po[i];
        }
        __syncthreads();
        if (t < 256) {
            #pragma unroll
            for (int dd = 0; dd < 2; dd++) {
                int d = dq * 16 + ch * 2 + dd;
                float s = 0.f;
                #pragma unroll
                for (int rr = 0; rr < 5; rr++)
                    s += psum[((rr * 4 + dq) * 16 + (xr >> 2)) * 8 + (xr & 3) * 2 + dd];
                ob[(size_t)d * HW_] = s;
            }
        }
        __syncthreads();
    }
}

extern "C" void kernel_launch(void* const* d_in, const int* in_sizes, int n_in,
                              void* d_out, int out_size) {
    const float* cur  = (const float*)d_in[0];
    const float* prev = (const float*)d_in[1];
    const float* pm   = (const float*)d_in[2];
    float* out = (float*)d_out;
    (void)in_sizes; (void)n_in; (void)out_size;

    const int smem = (4096 + 5 * 64 * PW) * 4;   // 108,544 B -> 2 CTAs/SM
    cudaFuncSetAttribute(fused_kernel, cudaFuncAttributeMaxDynamicSharedMemorySize, smem);

    zero_cnt_kernel<<<1, 32>>>();
    count_kernel<<<dim3(64, 2, N_), 256>>>(cur, prev);
    finalize_kernel<<<1, 32>>>();
    fused_kernel<<<dim3(H_, N_), NT, smem>>>(cur, prev, pm, out);
}